// round 16
// baseline (speedup 1.0000x reference)
#include <cuda_runtime.h>
#include <cuda_bf16.h>
#include <math.h>
#include <stdint.h>

#define BB   8
#define SS   2048
#define DD   1024
#define DKK  128
#define NTOK (BB * SS)          // 16384

// ---------------------------------------------------------------------------
// Scratch (allocation-free rule: __device__ globals)
// ---------------------------------------------------------------------------
static __device__ __nv_bfloat16 g_Wh[3 * DKK * DD], g_Wl[3 * DKK * DD];
static __device__ __nv_bfloat16 g_Qh[NTOK * DKK], g_Ql[NTOK * DKK];
static __device__ __nv_bfloat16 g_Kh[NTOK * DKK], g_Kl[NTOK * DKK];
static __device__ __nv_bfloat16 g_Vh[NTOK * DKK], g_Vl[NTOK * DKK];

// split-KV partials: 256 slots (8 batches x 16 split-qt x 2 halves)
static __device__ float g_pO[256 * 64 * 128];   // unnormalized O
static __device__ float g_pm[256 * 64];         // row max
static __device__ float g_pl[256 * 64];         // row sum
static __device__ int4  g_tasks[384];           // (b, qt, k0|k1<<8, slot|-1)
static __device__ int   g_cnt[128];             // per-pair arrival counters

// ---------------------------------------------------------------------------
// Helpers
// ---------------------------------------------------------------------------
__device__ __forceinline__ uint32_t smem_u32(const void* p) {
    uint32_t a;
    asm("{ .reg .u64 t; cvta.to.shared.u64 t, %1; cvt.u32.u64 %0, t; }"
        : "=r"(a) : "l"(p));
    return a;
}

__device__ __forceinline__ void ldsm4(uint32_t r[4], uint32_t addr) {
    asm volatile("ldmatrix.sync.aligned.m8n8.x4.shared.b16 {%0,%1,%2,%3}, [%4];"
                 : "=r"(r[0]), "=r"(r[1]), "=r"(r[2]), "=r"(r[3]) : "r"(addr));
}
__device__ __forceinline__ void ldsm4t(uint32_t r[4], uint32_t addr) {
    asm volatile("ldmatrix.sync.aligned.m8n8.x4.trans.shared.b16 {%0,%1,%2,%3}, [%4];"
                 : "=r"(r[0]), "=r"(r[1]), "=r"(r[2]), "=r"(r[3]) : "r"(addr));
}
__device__ __forceinline__ void mma16816(float c[4], const uint32_t a[4],
                                         uint32_t b0, uint32_t b1) {
    asm volatile(
        "mma.sync.aligned.m16n8k16.row.col.f32.bf16.bf16.f32 "
        "{%0,%1,%2,%3}, {%4,%5,%6,%7}, {%8,%9}, {%0,%1,%2,%3};"
        : "+f"(c[0]), "+f"(c[1]), "+f"(c[2]), "+f"(c[3])
        : "r"(a[0]), "r"(a[1]), "r"(a[2]), "r"(a[3]), "r"(b0), "r"(b1));
}

// Dekker split of a float pair into packed bf16x2 hi + lo residual
__device__ __forceinline__ void split2(float f0, float f1, uint32_t& h, uint32_t& l) {
    __nv_bfloat162 t = __floats2bfloat162_rn(f0, f1);
    h = *reinterpret_cast<uint32_t*>(&t);
    float r0 = __low2float(t), r1 = __high2float(t);
    __nv_bfloat162 u = __floats2bfloat162_rn(f0 - r0, f1 - r1);
    l = *reinterpret_cast<uint32_t*>(&u);
}

// ---------------------------------------------------------------------------
// Kernel 1: split W into hi/lo bf16 + build sorted attn task table + reset
// the per-pair merge counters (required fresh every launch / graph replay).
// ---------------------------------------------------------------------------
#define WN ((long long)DKK * DD)           // 131072

__global__ void convert_w_kernel(const float* __restrict__ Wq,
                                 const float* __restrict__ Wk,
                                 const float* __restrict__ Wv) {
    // Build attention task table, largest-first (1 thread; 384 entries).
    if (blockIdx.x == 0 && threadIdx.x == 0) {
        int idx = 0;
        for (int s = 16; s >= 1; s--) {
            for (int b = 0; b < 8; b++) {
                for (int qt = 16; qt < 32; qt++) {
                    const int N = qt + 1, mid = (N + 1) >> 1;
                    const int base = (((b << 4) + (qt - 16)) << 1);
                    if (mid == s)
                        g_tasks[idx++] = make_int4(b, qt, 0 | (mid << 8), base);
                    if (N - mid == s)
                        g_tasks[idx++] = make_int4(b, qt, mid | (N << 8), base + 1);
                }
                {
                    const int qt = s - 1;
                    g_tasks[idx++] = make_int4(b, qt, 0 | ((qt + 1) << 8), -1);
                }
            }
        }
    }
    // Reset merge counters each launch (block 1 to run parallel with table).
    if (blockIdx.x == 1 && threadIdx.x < 128) g_cnt[threadIdx.x] = 0;

    const long long i = (long long)blockIdx.x * blockDim.x + threadIdx.x;
    const long long e = i << 2;
    if (e >= 3 * WN) return;
    const float* src;
    long long o = e;
    if (o < WN)          src = Wq + o;
    else if (o < 2 * WN) src = Wk + (o - WN);
    else                 src = Wv + (o - 2 * WN);
    float4 v = *(const float4*)src;
    uint32_t h0, l0, h1, l1;
    split2(v.x, v.y, h0, l0);
    split2(v.z, v.w, h1, l1);
    *(uint2*)(g_Wh + e) = make_uint2(h0, h1);
    *(uint2*)(g_Wl + e) = make_uint2(l0, l1);
}

// ---------------------------------------------------------------------------
// Kernel 2: projection GEMM — R13 body (uint4 W loads) + masked-tile skip
// + Q pre-scaled by 1/sqrt(dk) in the epilogue.
// ---------------------------------------------------------------------------
#define PLD 72                                // smem stride (bf16 elems)
#define PROJ_SMEM (4 * 128 * PLD * 2)         // 73728 B

__global__ __launch_bounds__(256, 2) void proj_tc(const float* __restrict__ x,
                                                  const float* __restrict__ ctx,
                                                  const int* __restrict__ lens) {
    extern __shared__ __nv_bfloat16 psm[];
    __nv_bfloat16* sAh = psm;
    __nv_bfloat16* sAl = psm + 128 * PLD;
    __nv_bfloat16* sWh = psm + 2 * 128 * PLD;
    __nv_bfloat16* sWl = psm + 3 * 128 * PLD;
    const uint32_t aAh = smem_u32(sAh), aAl = smem_u32(sAl);
    const uint32_t aWh = smem_u32(sWh), aWl = smem_u32(sWl);

    const int which = blockIdx.y;                         // 0=Q,1=K,2=V
    const int m0cta = blockIdx.x * 128;
    const float* A = (which == 2) ? x : ctx;
    const __nv_bfloat16* Wh = g_Wh + (size_t)which * WN;
    const __nv_bfloat16* Wl = g_Wl + (size_t)which * WN;
    __nv_bfloat16* Oh = (which == 0) ? g_Qh : (which == 1) ? g_Kh : g_Vh;
    __nv_bfloat16* Ol = (which == 0) ? g_Ql : (which == 1) ? g_Kl : g_Vl;

    const int tid = threadIdx.x;
    const int batch = m0cta >> 11;
    const int len = lens[batch];
    const int tokbase = m0cta - (batch << 11);

    // Fully-masked tile: all 128 rows >= len. Output is exactly zero.
    if (tokbase >= len) {
        const uint4 z = make_uint4(0u, 0u, 0u, 0u);
        uint4* oh = (uint4*)(Oh + (size_t)m0cta * DKK);
        uint4* ol = (uint4*)(Ol + (size_t)m0cta * DKK);
#pragma unroll
        for (int i = 0; i < 8; i++) {
            const int idx = i * 256 + tid;
            oh[idx] = z;
            ol[idx] = z;
        }
        return;
    }

    const int w = tid >> 5, l = tid & 31;
    const int m0 = (w & 3) * 32;
    const int n0 = (w >> 2) * 64;

    const int arow = (l & 7) + 8 * ((l >> 3) & 1);
    const int acol = 8 * (l >> 4);
    const int brow = (l & 7) + 8 * (l >> 4);
    const int bcol = 8 * ((l >> 3) & 1);

    float c[2][8][4];
#pragma unroll
    for (int mf = 0; mf < 2; mf++)
#pragma unroll
        for (int nf = 0; nf < 8; nf++)
#pragma unroll
            for (int e = 0; e < 4; e++) c[mf][nf][e] = 0.f;

    for (int kc = 0; kc < 16; kc++) {
        const int kg = kc * 64;
        __syncthreads();
        // A: load 128x64 fp32 chunk, split-convert to hi/lo smem.
#pragma unroll
        for (int i = 0; i < 8; i++) {
            const int idx = i * 256 + tid;
            const int r = idx >> 4, c4 = (idx & 15) * 4;
            float4 v = *(const float4*)(A + (size_t)(m0cta + r) * DD + kg + c4);
            uint32_t h0, l0, h1, l1;
            split2(v.x, v.y, h0, l0);
            split2(v.z, v.w, h1, l1);
            *(uint2*)(sAh + r * PLD + c4) = make_uint2(h0, h1);
            *(uint2*)(sAl + r * PLD + c4) = make_uint2(l0, l1);
        }
        // W: copy 128x64 bf16 hi/lo chunks.
#pragma unroll
        for (int i = 0; i < 4; i++) {
            const int idx = i * 256 + tid;
            const int r = idx >> 3, cc = (idx & 7) * 8;
            const size_t gw = (size_t)r * DD + kg + cc;
            *(uint4*)(sWh + r * PLD + cc) = *(const uint4*)(Wh + gw);
            *(uint4*)(sWl + r * PLD + cc) = *(const uint4*)(Wl + gw);
        }
        __syncthreads();

#pragma unroll
        for (int ks = 0; ks < 4; ks++) {
            const int k0 = ks * 16;
            uint32_t ah[2][4], al[2][4];
#pragma unroll
            for (int mf = 0; mf < 2; mf++) {
                const uint32_t off = 2u * ((m0 + mf * 16 + arow) * PLD + k0 + acol);
                ldsm4(ah[mf], aAh + off);
                ldsm4(al[mf], aAl + off);
            }
#pragma unroll
            for (int bb = 0; bb < 4; bb++) {
                uint32_t bh[4], bl[4];
                const uint32_t off = 2u * ((n0 + bb * 16 + brow) * PLD + k0 + bcol);
                ldsm4(bh, aWh + off);
                ldsm4(bl, aWl + off);
#pragma unroll
                for (int mf = 0; mf < 2; mf++) {
                    mma16816(c[mf][2 * bb], ah[mf], bh[0], bh[1]);
                    mma16816(c[mf][2 * bb], ah[mf], bl[0], bl[1]);
                    mma16816(c[mf][2 * bb], al[mf], bh[0], bh[1]);
                    mma16816(c[mf][2 * bb + 1], ah[mf], bh[2], bh[3]);
                    mma16816(c[mf][2 * bb + 1], ah[mf], bl[2], bl[3]);
                    mma16816(c[mf][2 * bb + 1], al[mf], bh[2], bh[3]);
                }
            }
        }
    }

    // Epilogue: mask padded rows (Q additionally pre-scaled by 1/sqrt(dk)).
    const float sc = (which == 0) ? 0.08838834764831845f : 1.f;
#pragma unroll
    for (int mf = 0; mf < 2; mf++) {
        const int lr = m0 + mf * 16 + (l >> 2);
        const int gm0 = m0cta + lr, gm1 = gm0 + 8;
        const float msk0 = (tokbase + lr < len) ? sc : 0.f;
        const float msk1 = (tokbase + lr + 8 < len) ? sc : 0.f;
#pragma unroll
        for (int nf = 0; nf < 8; nf++) {
            const int col = n0 + nf * 8 + 2 * (l & 3);
            uint32_t h, lo;
            split2(c[mf][nf][0] * msk0, c[mf][nf][1] * msk0, h, lo);
            *(uint32_t*)(Oh + (size_t)gm0 * DKK + col) = h;
            *(uint32_t*)(Ol + (size_t)gm0 * DKK + col) = lo;
            split2(c[mf][nf][2] * msk1, c[mf][nf][3] * msk1, h, lo);
            *(uint32_t*)(Oh + (size_t)gm1 * DKK + col) = h;
            *(uint32_t*)(Ol + (size_t)gm1 * DKK + col) = lo;
        }
    }
}

// ---------------------------------------------------------------------------
// Kernel 3: flash attention — R15 split-KV body with FUSED merge:
// both halves write partials + arrive on a per-pair counter; the
// second-arriving CTA merges its register accumulator with the peer's
// partial and writes the final output (commutative => deterministic).
// ---------------------------------------------------------------------------
#define ALD 136                               // smem stride (bf16 elems)
#define TSZ (64 * ALD)                        // one tile, elems
#define ATTN_SMEM (6 * TSZ * 2)               // 104448 B

__global__ __launch_bounds__(128, 2) void attn_tc(const int* __restrict__ lens,
                                                  float* __restrict__ out) {
    extern __shared__ __nv_bfloat16 asm_[];
    __nv_bfloat16* sQh = asm_;
    __nv_bfloat16* sQl = asm_ + TSZ;
    __nv_bfloat16* sKh = asm_ + 2 * TSZ;
    __nv_bfloat16* sKl = asm_ + 3 * TSZ;
    __nv_bfloat16* sVh = asm_ + 4 * TSZ;
    __nv_bfloat16* sVl = asm_ + 5 * TSZ;
    const uint32_t aQh = smem_u32(sQh), aQl = smem_u32(sQl);
    const uint32_t aKh = smem_u32(sKh), aKl = smem_u32(sKl);
    const uint32_t aVh = smem_u32(sVh), aVl = smem_u32(sVl);

    const int4 tk = g_tasks[blockIdx.x];
    const int b = tk.x, qt = tk.y;
    const int k0 = tk.z & 0xff, k1 = tk.z >> 8;
    const int slot = tk.w;

    const int q0 = qt * 64;
    const int len = lens[b];
    const int tid = threadIdx.x;
    const int w = tid >> 5, l = tid & 31;
    const int m0 = w * 16;

    const int arow = (l & 7) + 8 * ((l >> 3) & 1);
    const int acol = 8 * (l >> 4);
    const int brow = (l & 7) + 8 * (l >> 4);
    const int bcol = 8 * ((l >> 3) & 1);

    // Load Q tile (64 x 128) hi/lo
#pragma unroll
    for (int i = 0; i < 8; i++) {
        const int idx = i * 128 + tid;
        const int rr = idx >> 4, cc = (idx & 15) * 8;
        const size_t g = (size_t)(b * SS + q0 + rr) * DKK + cc;
        *(uint4*)(sQh + rr * ALD + cc) = *(const uint4*)(g_Qh + g);
        *(uint4*)(sQl + rr * ALD + cc) = *(const uint4*)(g_Ql + g);
    }

    float o[16][4];
#pragma unroll
    for (int nf = 0; nf < 16; nf++)
#pragma unroll
        for (int e = 0; e < 4; e++) o[nf][e] = 0.f;
    float mI0 = -1e30f, mI1 = -1e30f, lI0 = 0.f, lI1 = 0.f;

    const int r0 = q0 + m0 + (l >> 2);
    const int r1 = r0 + 8;
    const int jend = min(k1, ((len - 1) >> 6) + 1);

    for (int jt = k0; jt < jend; jt++) {
        const int j0 = jt * 64;
        __syncthreads();
#pragma unroll
        for (int i = 0; i < 8; i++) {
            const int idx = i * 128 + tid;
            const int rr = idx >> 4, cc = (idx & 15) * 8;
            const size_t g = (size_t)(b * SS + j0 + rr) * DKK + cc;
            *(uint4*)(sKh + rr * ALD + cc) = *(const uint4*)(g_Kh + g);
            *(uint4*)(sKl + rr * ALD + cc) = *(const uint4*)(g_Kl + g);
            *(uint4*)(sVh + rr * ALD + cc) = *(const uint4*)(g_Vh + g);
            *(uint4*)(sVl + rr * ALD + cc) = *(const uint4*)(g_Vl + g);
        }
        __syncthreads();

        // ---- S = Q K^T (3-term split; scale pre-folded into Q) ----
        float s[8][4];
#pragma unroll
        for (int nf = 0; nf < 8; nf++)
#pragma unroll
            for (int e = 0; e < 4; e++) s[nf][e] = 0.f;

#pragma unroll
        for (int ks = 0; ks < 8; ks++) {
            const int k0c = ks * 16;
            uint32_t ah[4], al[4];
            const uint32_t offA = 2u * ((m0 + arow) * ALD + k0c + acol);
            ldsm4(ah, aQh + offA);
            ldsm4(al, aQl + offA);
#pragma unroll
            for (int bb = 0; bb < 4; bb++) {
                uint32_t bh[4], bl[4];
                const uint32_t offB = 2u * ((bb * 16 + brow) * ALD + k0c + bcol);
                ldsm4(bh, aKh + offB);
                ldsm4(bl, aKl + offB);
                mma16816(s[2 * bb], ah, bh[0], bh[1]);
                mma16816(s[2 * bb], ah, bl[0], bl[1]);
                mma16816(s[2 * bb], al, bh[0], bh[1]);
                mma16816(s[2 * bb + 1], ah, bh[2], bh[3]);
                mma16816(s[2 * bb + 1], ah, bl[2], bl[3]);
                mma16816(s[2 * bb + 1], al, bh[2], bh[3]);
            }
        }

        // ---- masks (boundary tiles only) ----
        if (!(j0 + 63 <= q0 && j0 + 63 < len)) {
#pragma unroll
            for (int nf = 0; nf < 8; nf++) {
                const int cj = j0 + nf * 8 + 2 * (l & 3);
                s[nf][0] = (cj     <= r0 && cj     < len) ? s[nf][0] : -1e30f;
                s[nf][1] = (cj + 1 <= r0 && cj + 1 < len) ? s[nf][1] : -1e30f;
                s[nf][2] = (cj     <= r1 && cj     < len) ? s[nf][2] : -1e30f;
                s[nf][3] = (cj + 1 <= r1 && cj + 1 < len) ? s[nf][3] : -1e30f;
            }
        }

        // ---- online softmax ----
        float mx0 = -1e30f, mx1 = -1e30f;
#pragma unroll
        for (int nf = 0; nf < 8; nf++) {
            mx0 = fmaxf(mx0, fmaxf(s[nf][0], s[nf][1]));
            mx1 = fmaxf(mx1, fmaxf(s[nf][2], s[nf][3]));
        }
        mx0 = fmaxf(mx0, __shfl_xor_sync(0xffffffffu, mx0, 1));
        mx0 = fmaxf(mx0, __shfl_xor_sync(0xffffffffu, mx0, 2));
        mx1 = fmaxf(mx1, __shfl_xor_sync(0xffffffffu, mx1, 1));
        mx1 = fmaxf(mx1, __shfl_xor_sync(0xffffffffu, mx1, 2));

        const float mn0 = fmaxf(mI0, mx0), mn1 = fmaxf(mI1, mx1);
        const float f0 = __expf(mI0 - mn0), f1 = __expf(mI1 - mn1);
        mI0 = mn0; mI1 = mn1;

        float sum0 = 0.f, sum1 = 0.f;
#pragma unroll
        for (int nf = 0; nf < 8; nf++) {
            s[nf][0] = __expf(s[nf][0] - mn0);
            s[nf][1] = __expf(s[nf][1] - mn0);
            s[nf][2] = __expf(s[nf][2] - mn1);
            s[nf][3] = __expf(s[nf][3] - mn1);
            sum0 += s[nf][0] + s[nf][1];
            sum1 += s[nf][2] + s[nf][3];
        }
        sum0 += __shfl_xor_sync(0xffffffffu, sum0, 1);
        sum0 += __shfl_xor_sync(0xffffffffu, sum0, 2);
        sum1 += __shfl_xor_sync(0xffffffffu, sum1, 1);
        sum1 += __shfl_xor_sync(0xffffffffu, sum1, 2);
        lI0 = lI0 * f0 + sum0;
        lI1 = lI1 * f1 + sum1;

#pragma unroll
        for (int nf = 0; nf < 16; nf++) {
            o[nf][0] *= f0; o[nf][1] *= f0;
            o[nf][2] *= f1; o[nf][3] *= f1;
        }

        uint32_t Ph[4][4], Pl[4][4];
#pragma unroll
        for (int t = 0; t < 4; t++) {
            split2(s[2 * t][0],     s[2 * t][1],     Ph[t][0], Pl[t][0]);
            split2(s[2 * t][2],     s[2 * t][3],     Ph[t][1], Pl[t][1]);
            split2(s[2 * t + 1][0], s[2 * t + 1][1], Ph[t][2], Pl[t][2]);
            split2(s[2 * t + 1][2], s[2 * t + 1][3], Ph[t][3], Pl[t][3]);
        }

        // ---- O += P V ----
#pragma unroll
        for (int t = 0; t < 4; t++) {
            const int jr = t * 16;
#pragma unroll
            for (int db = 0; db < 8; db++) {
                uint32_t vh[4], vl[4];
                const uint32_t offV = 2u * ((jr + arow) * ALD + db * 16 + acol);
                ldsm4t(vh, aVh + offV);
                ldsm4t(vl, aVl + offV);
                mma16816(o[2 * db], Ph[t], vh[0], vh[1]);
                mma16816(o[2 * db], Ph[t], vl[0], vl[1]);
                mma16816(o[2 * db], Pl[t], vh[0], vh[1]);
                mma16816(o[2 * db + 1], Ph[t], vh[2], vh[3]);
                mma16816(o[2 * db + 1], Ph[t], vl[2], vl[3]);
                mma16816(o[2 * db + 1], Pl[t], vh[2], vh[3]);
            }
        }
    }

    if (slot < 0) {
        // ---- solo epilogue: O /= l ----
        const float inv0 = 1.f / lI0, inv1 = 1.f / lI1;
#pragma unroll
        for (int nf = 0; nf < 16; nf++) {
            const int col = nf * 8 + 2 * (l & 3);
            *(float2*)(out + ((size_t)b * SS + r0) * DKK + col) =
                make_float2(o[nf][0] * inv0, o[nf][1] * inv0);
            *(float2*)(out + ((size_t)b * SS + r1) * DKK + col) =
                make_float2(o[nf][2] * inv1, o[nf][3] * inv1);
        }
        return;
    }

    // ---- split epilogue: publish partial, then last arriver merges ----
    const int lr0 = m0 + (l >> 2), lr1 = lr0 + 8;
    if ((l & 3) == 0) {
        g_pm[slot * 64 + lr0] = mI0;  g_pl[slot * 64 + lr0] = lI0;
        g_pm[slot * 64 + lr1] = mI1;  g_pl[slot * 64 + lr1] = lI1;
    }
#pragma unroll
    for (int nf = 0; nf < 16; nf++) {
        const int col = nf * 8 + 2 * (l & 3);
        *(float2*)(g_pO + ((size_t)slot * 64 + lr0) * 128 + col) =
            make_float2(o[nf][0], o[nf][1]);
        *(float2*)(g_pO + ((size_t)slot * 64 + lr1) * 128 + col) =
            make_float2(o[nf][2], o[nf][3]);
    }
    __threadfence();              // publish this thread's partial writes
    __syncthreads();              // all threads' fenced writes precede arrive
    __shared__ int s_old;
    if (tid == 0) s_old = atomicAdd(&g_cnt[slot >> 1], 1);
    __syncthreads();
    if (s_old == 0) return;       // first arriver: peer will merge

    // Second arriver: merge register accumulator with peer's partial.
    __threadfence();              // acquire side
    const int peer = slot ^ 1;
    const float mp0 = g_pm[peer * 64 + lr0], lp0 = g_pl[peer * 64 + lr0];
    const float mp1 = g_pm[peer * 64 + lr1], lp1 = g_pl[peer * 64 + lr1];
    const float M0 = fmaxf(mI0, mp0), M1 = fmaxf(mI1, mp1);
    const float wu0 = __expf(mI0 - M0), wp0 = __expf(mp0 - M0);
    const float wu1 = __expf(mI1 - M1), wp1 = __expf(mp1 - M1);
    const float inv0 = 1.f / (wu0 * lI0 + wp0 * lp0);
    const float inv1 = 1.f / (wu1 * lI1 + wp1 * lp1);
#pragma unroll
    for (int nf = 0; nf < 16; nf++) {
        const int col = nf * 8 + 2 * (l & 3);
        float2 p0 = *(const float2*)(g_pO + ((size_t)peer * 64 + lr0) * 128 + col);
        float2 p1 = *(const float2*)(g_pO + ((size_t)peer * 64 + lr1) * 128 + col);
        *(float2*)(out + ((size_t)b * SS + r0) * DKK + col) =
            make_float2((wu0 * o[nf][0] + wp0 * p0.x) * inv0,
                        (wu0 * o[nf][1] + wp0 * p0.y) * inv0);
        *(float2*)(out + ((size_t)b * SS + r1) * DKK + col) =
            make_float2((wu1 * o[nf][2] + wp1 * p1.x) * inv1,
                        (wu1 * o[nf][3] + wp1 * p1.y) * inv1);
    }
}

// ---------------------------------------------------------------------------
extern "C" void kernel_launch(void* const* d_in, const int* in_sizes, int n_in,
                              void* d_out, int out_size)
{
    const float* x   = (const float*)d_in[0];
    const float* ctx = (const float*)d_in[1];
    const float* Wq  = (const float*)d_in[2];
    const float* Wk  = (const float*)d_in[3];
    const float* Wv  = (const float*)d_in[4];
    const int* lens  = (const int*)d_in[5];
    float* out = (float*)d_out;

    cudaFuncSetAttribute(proj_tc, cudaFuncAttributeMaxDynamicSharedMemorySize,
                         PROJ_SMEM);
    cudaFuncSetAttribute(attn_tc, cudaFuncAttributeMaxDynamicSharedMemorySize,
                         ATTN_SMEM);

    convert_w_kernel<<<384, 256>>>(Wq, Wk, Wv);

    dim3 gp(NTOK / 128, 3);
    proj_tc<<<gp, 256, PROJ_SMEM>>>(x, ctx, lens);

    attn_tc<<<384, 128, ATTN_SMEM>>>(lens, out);
}

// round 17
// speedup vs baseline: 1.1519x; 1.1519x over previous
#include <cuda_runtime.h>
#include <cuda_bf16.h>
#include <math.h>
#include <stdint.h>

#define BB   8
#define SS   2048
#define DD   1024
#define DKK  128
#define NTOK (BB * SS)          // 16384

// ---------------------------------------------------------------------------
// Scratch (allocation-free rule: __device__ globals)
// ---------------------------------------------------------------------------
static __device__ __nv_bfloat16 g_Wh[3 * DKK * DD], g_Wl[3 * DKK * DD];
static __device__ __nv_bfloat16 g_Qh[NTOK * DKK], g_Ql[NTOK * DKK];
static __device__ __nv_bfloat16 g_Kh[NTOK * DKK], g_Kl[NTOK * DKK];
static __device__ __nv_bfloat16 g_Vh[NTOK * DKK], g_Vl[NTOK * DKK];

// split-KV partials: 256 slots (8 batches x 16 split-qt x 2 halves)
static __device__ float g_pO[256 * 64 * 128];   // unnormalized O
static __device__ float g_pm[256 * 64];         // row max
static __device__ float g_pl[256 * 64];         // row sum
static __device__ int   g_cnt[128];             // per-pair arrival counters

// ---------------------------------------------------------------------------
// Helpers
// ---------------------------------------------------------------------------
__device__ __forceinline__ uint32_t smem_u32(const void* p) {
    uint32_t a;
    asm("{ .reg .u64 t; cvta.to.shared.u64 t, %1; cvt.u32.u64 %0, t; }"
        : "=r"(a) : "l"(p));
    return a;
}

__device__ __forceinline__ void ldsm4(uint32_t r[4], uint32_t addr) {
    asm volatile("ldmatrix.sync.aligned.m8n8.x4.shared.b16 {%0,%1,%2,%3}, [%4];"
                 : "=r"(r[0]), "=r"(r[1]), "=r"(r[2]), "=r"(r[3]) : "r"(addr));
}
__device__ __forceinline__ void ldsm4t(uint32_t r[4], uint32_t addr) {
    asm volatile("ldmatrix.sync.aligned.m8n8.x4.trans.shared.b16 {%0,%1,%2,%3}, [%4];"
                 : "=r"(r[0]), "=r"(r[1]), "=r"(r[2]), "=r"(r[3]) : "r"(addr));
}
__device__ __forceinline__ void mma16816(float c[4], const uint32_t a[4],
                                         uint32_t b0, uint32_t b1) {
    asm volatile(
        "mma.sync.aligned.m16n8k16.row.col.f32.bf16.bf16.f32 "
        "{%0,%1,%2,%3}, {%4,%5,%6,%7}, {%8,%9}, {%0,%1,%2,%3};"
        : "+f"(c[0]), "+f"(c[1]), "+f"(c[2]), "+f"(c[3])
        : "r"(a[0]), "r"(a[1]), "r"(a[2]), "r"(a[3]), "r"(b0), "r"(b1));
}

// Dekker split of a float pair into packed bf16x2 hi + lo residual
__device__ __forceinline__ void split2(float f0, float f1, uint32_t& h, uint32_t& l) {
    __nv_bfloat162 t = __floats2bfloat162_rn(f0, f1);
    h = *reinterpret_cast<uint32_t*>(&t);
    float r0 = __low2float(t), r1 = __high2float(t);
    __nv_bfloat162 u = __floats2bfloat162_rn(f0 - r0, f1 - r1);
    l = *reinterpret_cast<uint32_t*>(&u);
}

// ---------------------------------------------------------------------------
// Closed-form task decode (largest-first schedule), pure fn of t in [0,384).
// Groups by chunk size s: {16:32, 15..9:40 each, 8:16, 7..1:8 each} tasks.
// Within (s,b): [F(2s-2), F(2s-1), S(2s-1), S(2s), solo(s-1)] (where defined).
// ---------------------------------------------------------------------------
__device__ __forceinline__ void decode_task(int t, int& b, int& qt,
                                            int& k0, int& k1, int& slot) {
    int s, base, c;
    if (t < 32)       { s = 16;                 base = 0;                 c = 4; }
    else if (t < 312) { s = 15 - (t - 32) / 40; base = 32 + (15 - s) * 40; c = 5; }
    else if (t < 328) { s = 8;                  base = 312;               c = 2; }
    else              { s = 7 - (t - 328) / 8;  base = 328 + (7 - s) * 8; c = 1; }
    const int r = t - base;
    b = r / c;
    const int j = r - b * c;

    if (s == 16) {
        if (j == 0)      { qt = 30; k0 = 0;  k1 = 16; slot = ((b << 4) + 14) * 2; }
        else if (j == 1) { qt = 31; k0 = 0;  k1 = 16; slot = ((b << 4) + 15) * 2; }
        else if (j == 2) { qt = 31; k0 = 16; k1 = 32; slot = ((b << 4) + 15) * 2 + 1; }
        else             { qt = 15; k0 = 0;  k1 = 16; slot = -1; }
    } else if (s >= 9) {
        if (j == 0)      { qt = 2 * s - 2; k0 = 0;     k1 = s;         slot = ((b << 4) + qt - 16) * 2; }
        else if (j == 1) { qt = 2 * s - 1; k0 = 0;     k1 = s;         slot = ((b << 4) + qt - 16) * 2; }
        else if (j == 2) { qt = 2 * s - 1; k0 = s;     k1 = 2 * s;     slot = ((b << 4) + qt - 16) * 2 + 1; }
        else if (j == 3) { qt = 2 * s;     k0 = s + 1; k1 = 2 * s + 1; slot = ((b << 4) + qt - 16) * 2 + 1; }
        else             { qt = s - 1;     k0 = 0;     k1 = s;         slot = -1; }
    } else if (s == 8) {
        if (j == 0)      { qt = 16; k0 = 9; k1 = 17; slot = ((b << 4) + 0) * 2 + 1; }
        else             { qt = 7;  k0 = 0; k1 = 8;  slot = -1; }
    } else {
        qt = s - 1; k0 = 0; k1 = s; slot = -1;
    }
}

// ---------------------------------------------------------------------------
// Kernel 1: split W into hi/lo bf16 + reset per-pair merge counters.
// ---------------------------------------------------------------------------
#define WN ((long long)DKK * DD)           // 131072

__global__ void convert_w_kernel(const float* __restrict__ Wq,
                                 const float* __restrict__ Wk,
                                 const float* __restrict__ Wv) {
    // Reset merge counters each launch (block 1; tiny, parallel).
    if (blockIdx.x == 1 && threadIdx.x < 128) g_cnt[threadIdx.x] = 0;

    const long long i = (long long)blockIdx.x * blockDim.x + threadIdx.x;
    const long long e = i << 2;
    if (e >= 3 * WN) return;
    const float* src;
    long long o = e;
    if (o < WN)          src = Wq + o;
    else if (o < 2 * WN) src = Wk + (o - WN);
    else                 src = Wv + (o - 2 * WN);
    float4 v = *(const float4*)src;
    uint32_t h0, l0, h1, l1;
    split2(v.x, v.y, h0, l0);
    split2(v.z, v.w, h1, l1);
    *(uint2*)(g_Wh + e) = make_uint2(h0, h1);
    *(uint2*)(g_Wl + e) = make_uint2(l0, l1);
}

// ---------------------------------------------------------------------------
// Kernel 2: projection GEMM — R15 body (uint4 W loads) + masked-tile skip
// + Q pre-scaled by 1/sqrt(dk) in the epilogue.
// ---------------------------------------------------------------------------
#define PLD 72                                // smem stride (bf16 elems)
#define PROJ_SMEM (4 * 128 * PLD * 2)         // 73728 B

__global__ __launch_bounds__(256, 2) void proj_tc(const float* __restrict__ x,
                                                  const float* __restrict__ ctx,
                                                  const int* __restrict__ lens) {
    extern __shared__ __nv_bfloat16 psm[];
    __nv_bfloat16* sAh = psm;
    __nv_bfloat16* sAl = psm + 128 * PLD;
    __nv_bfloat16* sWh = psm + 2 * 128 * PLD;
    __nv_bfloat16* sWl = psm + 3 * 128 * PLD;
    const uint32_t aAh = smem_u32(sAh), aAl = smem_u32(sAl);
    const uint32_t aWh = smem_u32(sWh), aWl = smem_u32(sWl);

    const int which = blockIdx.y;                         // 0=Q,1=K,2=V
    const int m0cta = blockIdx.x * 128;
    const float* A = (which == 2) ? x : ctx;
    const __nv_bfloat16* Wh = g_Wh + (size_t)which * WN;
    const __nv_bfloat16* Wl = g_Wl + (size_t)which * WN;
    __nv_bfloat16* Oh = (which == 0) ? g_Qh : (which == 1) ? g_Kh : g_Vh;
    __nv_bfloat16* Ol = (which == 0) ? g_Ql : (which == 1) ? g_Kl : g_Vl;

    const int tid = threadIdx.x;
    const int batch = m0cta >> 11;
    const int len = lens[batch];
    const int tokbase = m0cta - (batch << 11);

    // Fully-masked tile: all 128 rows >= len. Output is exactly zero.
    if (tokbase >= len) {
        const uint4 z = make_uint4(0u, 0u, 0u, 0u);
        uint4* oh = (uint4*)(Oh + (size_t)m0cta * DKK);
        uint4* ol = (uint4*)(Ol + (size_t)m0cta * DKK);
#pragma unroll
        for (int i = 0; i < 8; i++) {
            const int idx = i * 256 + tid;
            oh[idx] = z;
            ol[idx] = z;
        }
        return;
    }

    const int w = tid >> 5, l = tid & 31;
    const int m0 = (w & 3) * 32;
    const int n0 = (w >> 2) * 64;

    const int arow = (l & 7) + 8 * ((l >> 3) & 1);
    const int acol = 8 * (l >> 4);
    const int brow = (l & 7) + 8 * (l >> 4);
    const int bcol = 8 * ((l >> 3) & 1);

    float c[2][8][4];
#pragma unroll
    for (int mf = 0; mf < 2; mf++)
#pragma unroll
        for (int nf = 0; nf < 8; nf++)
#pragma unroll
            for (int e = 0; e < 4; e++) c[mf][nf][e] = 0.f;

    for (int kc = 0; kc < 16; kc++) {
        const int kg = kc * 64;
        __syncthreads();
        // A: load 128x64 fp32 chunk, split-convert to hi/lo smem.
#pragma unroll
        for (int i = 0; i < 8; i++) {
            const int idx = i * 256 + tid;
            const int r = idx >> 4, c4 = (idx & 15) * 4;
            float4 v = *(const float4*)(A + (size_t)(m0cta + r) * DD + kg + c4);
            uint32_t h0, l0, h1, l1;
            split2(v.x, v.y, h0, l0);
            split2(v.z, v.w, h1, l1);
            *(uint2*)(sAh + r * PLD + c4) = make_uint2(h0, h1);
            *(uint2*)(sAl + r * PLD + c4) = make_uint2(l0, l1);
        }
        // W: copy 128x64 bf16 hi/lo chunks.
#pragma unroll
        for (int i = 0; i < 4; i++) {
            const int idx = i * 256 + tid;
            const int r = idx >> 3, cc = (idx & 7) * 8;
            const size_t gw = (size_t)r * DD + kg + cc;
            *(uint4*)(sWh + r * PLD + cc) = *(const uint4*)(Wh + gw);
            *(uint4*)(sWl + r * PLD + cc) = *(const uint4*)(Wl + gw);
        }
        __syncthreads();

#pragma unroll
        for (int ks = 0; ks < 4; ks++) {
            const int k0 = ks * 16;
            uint32_t ah[2][4], al[2][4];
#pragma unroll
            for (int mf = 0; mf < 2; mf++) {
                const uint32_t off = 2u * ((m0 + mf * 16 + arow) * PLD + k0 + acol);
                ldsm4(ah[mf], aAh + off);
                ldsm4(al[mf], aAl + off);
            }
#pragma unroll
            for (int bb = 0; bb < 4; bb++) {
                uint32_t bh[4], bl[4];
                const uint32_t off = 2u * ((n0 + bb * 16 + brow) * PLD + k0 + bcol);
                ldsm4(bh, aWh + off);
                ldsm4(bl, aWl + off);
#pragma unroll
                for (int mf = 0; mf < 2; mf++) {
                    mma16816(c[mf][2 * bb], ah[mf], bh[0], bh[1]);
                    mma16816(c[mf][2 * bb], ah[mf], bl[0], bl[1]);
                    mma16816(c[mf][2 * bb], al[mf], bh[0], bh[1]);
                    mma16816(c[mf][2 * bb + 1], ah[mf], bh[2], bh[3]);
                    mma16816(c[mf][2 * bb + 1], ah[mf], bl[2], bl[3]);
                    mma16816(c[mf][2 * bb + 1], al[mf], bh[2], bh[3]);
                }
            }
        }
    }

    // Epilogue: mask padded rows (Q additionally pre-scaled by 1/sqrt(dk)).
    const float sc = (which == 0) ? 0.08838834764831845f : 1.f;
#pragma unroll
    for (int mf = 0; mf < 2; mf++) {
        const int lr = m0 + mf * 16 + (l >> 2);
        const int gm0 = m0cta + lr, gm1 = gm0 + 8;
        const float msk0 = (tokbase + lr < len) ? sc : 0.f;
        const float msk1 = (tokbase + lr + 8 < len) ? sc : 0.f;
#pragma unroll
        for (int nf = 0; nf < 8; nf++) {
            const int col = n0 + nf * 8 + 2 * (l & 3);
            uint32_t h, lo;
            split2(c[mf][nf][0] * msk0, c[mf][nf][1] * msk0, h, lo);
            *(uint32_t*)(Oh + (size_t)gm0 * DKK + col) = h;
            *(uint32_t*)(Ol + (size_t)gm0 * DKK + col) = lo;
            split2(c[mf][nf][2] * msk1, c[mf][nf][3] * msk1, h, lo);
            *(uint32_t*)(Oh + (size_t)gm1 * DKK + col) = h;
            *(uint32_t*)(Ol + (size_t)gm1 * DKK + col) = lo;
        }
    }
}

// ---------------------------------------------------------------------------
// Kernel 3: flash attention — split-KV with inline task decode + fused merge
// (last-arriving CTA of each pair merges its register accumulator with the
//  peer's published partial; commutative => deterministic).
// ---------------------------------------------------------------------------
#define ALD 136                               // smem stride (bf16 elems)
#define TSZ (64 * ALD)                        // one tile, elems
#define ATTN_SMEM (6 * TSZ * 2)               // 104448 B

__global__ __launch_bounds__(128, 2) void attn_tc(const int* __restrict__ lens,
                                                  float* __restrict__ out) {
    extern __shared__ __nv_bfloat16 asm_[];
    __nv_bfloat16* sQh = asm_;
    __nv_bfloat16* sQl = asm_ + TSZ;
    __nv_bfloat16* sKh = asm_ + 2 * TSZ;
    __nv_bfloat16* sKl = asm_ + 3 * TSZ;
    __nv_bfloat16* sVh = asm_ + 4 * TSZ;
    __nv_bfloat16* sVl = asm_ + 5 * TSZ;
    const uint32_t aQh = smem_u32(sQh), aQl = smem_u32(sQl);
    const uint32_t aKh = smem_u32(sKh), aKl = smem_u32(sKl);
    const uint32_t aVh = smem_u32(sVh), aVl = smem_u32(sVl);

    int b, qt, k0, k1, slot;
    decode_task(blockIdx.x, b, qt, k0, k1, slot);

    const int q0 = qt * 64;
    const int len = lens[b];
    const int tid = threadIdx.x;
    const int w = tid >> 5, l = tid & 31;
    const int m0 = w * 16;

    const int arow = (l & 7) + 8 * ((l >> 3) & 1);
    const int acol = 8 * (l >> 4);
    const int brow = (l & 7) + 8 * (l >> 4);
    const int bcol = 8 * ((l >> 3) & 1);

    // Load Q tile (64 x 128) hi/lo
#pragma unroll
    for (int i = 0; i < 8; i++) {
        const int idx = i * 128 + tid;
        const int rr = idx >> 4, cc = (idx & 15) * 8;
        const size_t g = (size_t)(b * SS + q0 + rr) * DKK + cc;
        *(uint4*)(sQh + rr * ALD + cc) = *(const uint4*)(g_Qh + g);
        *(uint4*)(sQl + rr * ALD + cc) = *(const uint4*)(g_Ql + g);
    }

    float o[16][4];
#pragma unroll
    for (int nf = 0; nf < 16; nf++)
#pragma unroll
        for (int e = 0; e < 4; e++) o[nf][e] = 0.f;
    float mI0 = -1e30f, mI1 = -1e30f, lI0 = 0.f, lI1 = 0.f;

    const int r0 = q0 + m0 + (l >> 2);
    const int r1 = r0 + 8;
    const int jend = min(k1, ((len - 1) >> 6) + 1);

    for (int jt = k0; jt < jend; jt++) {
        const int j0 = jt * 64;
        __syncthreads();
#pragma unroll
        for (int i = 0; i < 8; i++) {
            const int idx = i * 128 + tid;
            const int rr = idx >> 4, cc = (idx & 15) * 8;
            const size_t g = (size_t)(b * SS + j0 + rr) * DKK + cc;
            *(uint4*)(sKh + rr * ALD + cc) = *(const uint4*)(g_Kh + g);
            *(uint4*)(sKl + rr * ALD + cc) = *(const uint4*)(g_Kl + g);
            *(uint4*)(sVh + rr * ALD + cc) = *(const uint4*)(g_Vh + g);
            *(uint4*)(sVl + rr * ALD + cc) = *(const uint4*)(g_Vl + g);
        }
        __syncthreads();

        // ---- S = Q K^T (3-term split; scale pre-folded into Q) ----
        float s[8][4];
#pragma unroll
        for (int nf = 0; nf < 8; nf++)
#pragma unroll
            for (int e = 0; e < 4; e++) s[nf][e] = 0.f;

#pragma unroll
        for (int ks = 0; ks < 8; ks++) {
            const int k0c = ks * 16;
            uint32_t ah[4], al[4];
            const uint32_t offA = 2u * ((m0 + arow) * ALD + k0c + acol);
            ldsm4(ah, aQh + offA);
            ldsm4(al, aQl + offA);
#pragma unroll
            for (int bb = 0; bb < 4; bb++) {
                uint32_t bh[4], bl[4];
                const uint32_t offB = 2u * ((bb * 16 + brow) * ALD + k0c + bcol);
                ldsm4(bh, aKh + offB);
                ldsm4(bl, aKl + offB);
                mma16816(s[2 * bb], ah, bh[0], bh[1]);
                mma16816(s[2 * bb], ah, bl[0], bl[1]);
                mma16816(s[2 * bb], al, bh[0], bh[1]);
                mma16816(s[2 * bb + 1], ah, bh[2], bh[3]);
                mma16816(s[2 * bb + 1], ah, bl[2], bl[3]);
                mma16816(s[2 * bb + 1], al, bh[2], bh[3]);
            }
        }

        // ---- masks (boundary tiles only) ----
        if (!(j0 + 63 <= q0 && j0 + 63 < len)) {
#pragma unroll
            for (int nf = 0; nf < 8; nf++) {
                const int cj = j0 + nf * 8 + 2 * (l & 3);
                s[nf][0] = (cj     <= r0 && cj     < len) ? s[nf][0] : -1e30f;
                s[nf][1] = (cj + 1 <= r0 && cj + 1 < len) ? s[nf][1] : -1e30f;
                s[nf][2] = (cj     <= r1 && cj     < len) ? s[nf][2] : -1e30f;
                s[nf][3] = (cj + 1 <= r1 && cj + 1 < len) ? s[nf][3] : -1e30f;
            }
        }

        // ---- online softmax ----
        float mx0 = -1e30f, mx1 = -1e30f;
#pragma unroll
        for (int nf = 0; nf < 8; nf++) {
            mx0 = fmaxf(mx0, fmaxf(s[nf][0], s[nf][1]));
            mx1 = fmaxf(mx1, fmaxf(s[nf][2], s[nf][3]));
        }
        mx0 = fmaxf(mx0, __shfl_xor_sync(0xffffffffu, mx0, 1));
        mx0 = fmaxf(mx0, __shfl_xor_sync(0xffffffffu, mx0, 2));
        mx1 = fmaxf(mx1, __shfl_xor_sync(0xffffffffu, mx1, 1));
        mx1 = fmaxf(mx1, __shfl_xor_sync(0xffffffffu, mx1, 2));

        const float mn0 = fmaxf(mI0, mx0), mn1 = fmaxf(mI1, mx1);
        const float f0 = __expf(mI0 - mn0), f1 = __expf(mI1 - mn1);
        mI0 = mn0; mI1 = mn1;

        float sum0 = 0.f, sum1 = 0.f;
#pragma unroll
        for (int nf = 0; nf < 8; nf++) {
            s[nf][0] = __expf(s[nf][0] - mn0);
            s[nf][1] = __expf(s[nf][1] - mn0);
            s[nf][2] = __expf(s[nf][2] - mn1);
            s[nf][3] = __expf(s[nf][3] - mn1);
            sum0 += s[nf][0] + s[nf][1];
            sum1 += s[nf][2] + s[nf][3];
        }
        sum0 += __shfl_xor_sync(0xffffffffu, sum0, 1);
        sum0 += __shfl_xor_sync(0xffffffffu, sum0, 2);
        sum1 += __shfl_xor_sync(0xffffffffu, sum1, 1);
        sum1 += __shfl_xor_sync(0xffffffffu, sum1, 2);
        lI0 = lI0 * f0 + sum0;
        lI1 = lI1 * f1 + sum1;

#pragma unroll
        for (int nf = 0; nf < 16; nf++) {
            o[nf][0] *= f0; o[nf][1] *= f0;
            o[nf][2] *= f1; o[nf][3] *= f1;
        }

        uint32_t Ph[4][4], Pl[4][4];
#pragma unroll
        for (int t = 0; t < 4; t++) {
            split2(s[2 * t][0],     s[2 * t][1],     Ph[t][0], Pl[t][0]);
            split2(s[2 * t][2],     s[2 * t][3],     Ph[t][1], Pl[t][1]);
            split2(s[2 * t + 1][0], s[2 * t + 1][1], Ph[t][2], Pl[t][2]);
            split2(s[2 * t + 1][2], s[2 * t + 1][3], Ph[t][3], Pl[t][3]);
        }

        // ---- O += P V ----
#pragma unroll
        for (int t = 0; t < 4; t++) {
            const int jr = t * 16;
#pragma unroll
            for (int db = 0; db < 8; db++) {
                uint32_t vh[4], vl[4];
                const uint32_t offV = 2u * ((jr + arow) * ALD + db * 16 + acol);
                ldsm4t(vh, aVh + offV);
                ldsm4t(vl, aVl + offV);
                mma16816(o[2 * db], Ph[t], vh[0], vh[1]);
                mma16816(o[2 * db], Ph[t], vl[0], vl[1]);
                mma16816(o[2 * db], Pl[t], vh[0], vh[1]);
                mma16816(o[2 * db + 1], Ph[t], vh[2], vh[3]);
                mma16816(o[2 * db + 1], Ph[t], vl[2], vl[3]);
                mma16816(o[2 * db + 1], Pl[t], vh[2], vh[3]);
            }
        }
    }

    if (slot < 0) {
        // ---- solo epilogue: O /= l ----
        const float inv0 = 1.f / lI0, inv1 = 1.f / lI1;
#pragma unroll
        for (int nf = 0; nf < 16; nf++) {
            const int col = nf * 8 + 2 * (l & 3);
            *(float2*)(out + ((size_t)b * SS + r0) * DKK + col) =
                make_float2(o[nf][0] * inv0, o[nf][1] * inv0);
            *(float2*)(out + ((size_t)b * SS + r1) * DKK + col) =
                make_float2(o[nf][2] * inv1, o[nf][3] * inv1);
        }
        return;
    }

    // ---- split epilogue: publish partial, then last arriver merges ----
    const int lr0 = m0 + (l >> 2), lr1 = lr0 + 8;
    if ((l & 3) == 0) {
        g_pm[slot * 64 + lr0] = mI0;  g_pl[slot * 64 + lr0] = lI0;
        g_pm[slot * 64 + lr1] = mI1;  g_pl[slot * 64 + lr1] = lI1;
    }
#pragma unroll
    for (int nf = 0; nf < 16; nf++) {
        const int col = nf * 8 + 2 * (l & 3);
        *(float2*)(g_pO + ((size_t)slot * 64 + lr0) * 128 + col) =
            make_float2(o[nf][0], o[nf][1]);
        *(float2*)(g_pO + ((size_t)slot * 64 + lr1) * 128 + col) =
            make_float2(o[nf][2], o[nf][3]);
    }
    __threadfence();              // publish this thread's partial writes
    __syncthreads();              // all threads' fenced writes precede arrive
    __shared__ int s_old;
    if (tid == 0) s_old = atomicAdd(&g_cnt[slot >> 1], 1);
    __syncthreads();
    if (s_old == 0) return;       // first arriver: peer will merge

    // Second arriver: merge register accumulator with peer's partial.
    __threadfence();              // acquire side
    const int peer = slot ^ 1;
    const float mp0 = g_pm[peer * 64 + lr0], lp0 = g_pl[peer * 64 + lr0];
    const float mp1 = g_pm[peer * 64 + lr1], lp1 = g_pl[peer * 64 + lr1];
    const float M0 = fmaxf(mI0, mp0), M1 = fmaxf(mI1, mp1);
    const float wu0 = __expf(mI0 - M0), wp0 = __expf(mp0 - M0);
    const float wu1 = __expf(mI1 - M1), wp1 = __expf(mp1 - M1);
    const float inv0 = 1.f / (wu0 * lI0 + wp0 * lp0);
    const float inv1 = 1.f / (wu1 * lI1 + wp1 * lp1);
#pragma unroll
    for (int nf = 0; nf < 16; nf++) {
        const int col = nf * 8 + 2 * (l & 3);
        float2 p0 = *(const float2*)(g_pO + ((size_t)peer * 64 + lr0) * 128 + col);
        float2 p1 = *(const float2*)(g_pO + ((size_t)peer * 64 + lr1) * 128 + col);
        *(float2*)(out + ((size_t)b * SS + r0) * DKK + col) =
            make_float2((wu0 * o[nf][0] + wp0 * p0.x) * inv0,
                        (wu0 * o[nf][1] + wp0 * p0.y) * inv0);
        *(float2*)(out + ((size_t)b * SS + r1) * DKK + col) =
            make_float2((wu1 * o[nf][2] + wp1 * p1.x) * inv1,
                        (wu1 * o[nf][3] + wp1 * p1.y) * inv1);
    }
}

// ---------------------------------------------------------------------------
extern "C" void kernel_launch(void* const* d_in, const int* in_sizes, int n_in,
                              void* d_out, int out_size)
{
    const float* x   = (const float*)d_in[0];
    const float* ctx = (const float*)d_in[1];
    const float* Wq  = (const float*)d_in[2];
    const float* Wk  = (const float*)d_in[3];
    const float* Wv  = (const float*)d_in[4];
    const int* lens  = (const int*)d_in[5];
    float* out = (float*)d_out;

    cudaFuncSetAttribute(proj_tc, cudaFuncAttributeMaxDynamicSharedMemorySize,
                         PROJ_SMEM);
    cudaFuncSetAttribute(attn_tc, cudaFuncAttributeMaxDynamicSharedMemorySize,
                         ATTN_SMEM);

    convert_w_kernel<<<384, 256>>>(Wq, Wk, Wv);

    dim3 gp(NTOK / 128, 3);
    proj_tc<<<gp, 256, PROJ_SMEM>>>(x, ctx, lens);

    attn_tc<<<384, 128, ATTN_SMEM>>>(lens, out);
}